// round 1
// baseline (speedup 1.0000x reference)
#include <cuda_runtime.h>
#include <math.h>

#define B_ 8
#define L_ 1024
#define D_ 256
#define U_ 256

typedef unsigned long long ull;

// ---------------- scratch (device globals; no allocation allowed) ----------
__device__ float g_EW[D_ * U_];          // E @ Wx            (256 KB)
__device__ float g_rnorm[B_ * L_];       // 1/max(rowsum,eps) (32 KB)
__device__ float g_t[B_ * L_ * U_];      // (seq@EW)*rnorm    (8 MB)
__device__ float g_xproj[B_ * L_ * U_];  // G^T @ t           (8 MB)

// ---------------- packed f32x2 helpers (sm_103a) ----------------------------
__device__ __forceinline__ ull pk2(float lo, float hi) {
    ull r; asm("mov.b64 %0,{%1,%2};" : "=l"(r) : "f"(lo), "f"(hi)); return r;
}
__device__ __forceinline__ void ffma2(ull& d, ull a, ull b) {
    asm("fma.rn.f32x2 %0,%1,%2,%0;" : "+l"(d) : "l"(a), "l"(b));
}
__device__ __forceinline__ float2 up2(ull a) {
    float lo, hi; asm("mov.b64 {%0,%1},%2;" : "=f"(lo), "=f"(hi) : "l"(a));
    float2 r; r.x = lo; r.y = hi; return r;
}

// ---------------- 1) rnorm[b,l] = 1 / max(sum_m graph[b,l,m], 1e-7) ---------
__global__ __launch_bounds__(256) void norm_kernel(const float* __restrict__ graph,
                                                   float* __restrict__ rnorm) {
    int warp = (blockIdx.x * blockDim.x + threadIdx.x) >> 5;
    int lane = threadIdx.x & 31;
    if (warp >= B_ * L_) return;
    const float4* row = (const float4*)(graph + (size_t)warp * L_);
    float s = 0.f;
#pragma unroll
    for (int i = lane; i < L_ / 4; i += 32) {
        float4 v = row[i];
        s += (v.x + v.y) + (v.z + v.w);
    }
#pragma unroll
    for (int o = 16; o; o >>= 1) s += __shfl_xor_sync(0xffffffffu, s, o);
    if (lane == 0) rnorm[warp] = 1.f / fmaxf(s, 1e-7f);
}

// ---------------- 2) GEMM NN: C[M,N] = A[M,K] @ B[K,N] (* rowscale) ---------
// 128x128 tile, BK=16, 256 threads, 8x8 micro-tile, f32x2 FMAs.
__global__ __launch_bounds__(256) void gemm_nn(const float* __restrict__ A,
                                               const float* __restrict__ Bm,
                                               float* __restrict__ C, int K,
                                               const float* __restrict__ rowscale) {
    __shared__ float As[16][128];
    __shared__ float Bs[16][128];
    const int N = 256;
    const int m0 = blockIdx.y * 128, n0 = blockIdx.x * 128;
    const int t = threadIdx.x;
    const int tx = t & 15, ty = t >> 4;

    ull acc[8][4];
#pragma unroll
    for (int i = 0; i < 8; i++)
#pragma unroll
        for (int j = 0; j < 4; j++) acc[i][j] = 0ull;

    for (int k0 = 0; k0 < K; k0 += 16) {
        __syncthreads();
#pragma unroll
        for (int i = 0; i < 2; i++) {
            int f4 = t + i * 256;
            int m = f4 >> 2, kg = f4 & 3;
            float4 va = *(const float4*)(A + (size_t)(m0 + m) * K + k0 + kg * 4);
            As[kg * 4 + 0][m] = va.x;
            As[kg * 4 + 1][m] = va.y;
            As[kg * 4 + 2][m] = va.z;
            As[kg * 4 + 3][m] = va.w;
            int kk = f4 >> 5, ng = f4 & 31;
            *(float4*)&Bs[kk][ng * 4] =
                *(const float4*)(Bm + (size_t)(k0 + kk) * N + n0 + ng * 4);
        }
        __syncthreads();
#pragma unroll
        for (int kk = 0; kk < 16; kk++) {
            float4 a0 = *(float4*)&As[kk][ty * 8];
            float4 a1 = *(float4*)&As[kk][ty * 8 + 4];
            float4 b0 = *(float4*)&Bs[kk][tx * 8];
            float4 b1 = *(float4*)&Bs[kk][tx * 8 + 4];
            ull bp0 = pk2(b0.x, b0.y), bp1 = pk2(b0.z, b0.w);
            ull bp2 = pk2(b1.x, b1.y), bp3 = pk2(b1.z, b1.w);
            float av[8] = {a0.x, a0.y, a0.z, a0.w, a1.x, a1.y, a1.z, a1.w};
#pragma unroll
            for (int i = 0; i < 8; i++) {
                ull ad = pk2(av[i], av[i]);
                ffma2(acc[i][0], ad, bp0);
                ffma2(acc[i][1], ad, bp1);
                ffma2(acc[i][2], ad, bp2);
                ffma2(acc[i][3], ad, bp3);
            }
        }
    }
#pragma unroll
    for (int i = 0; i < 8; i++) {
        int row = m0 + ty * 8 + i;
        float sc = rowscale ? rowscale[row] : 1.f;
        float2 v0 = up2(acc[i][0]), v1 = up2(acc[i][1]);
        float2 v2 = up2(acc[i][2]), v3 = up2(acc[i][3]);
        float4 o0 = make_float4(v0.x * sc, v0.y * sc, v1.x * sc, v1.y * sc);
        float4 o1 = make_float4(v2.x * sc, v2.y * sc, v3.x * sc, v3.y * sc);
        *(float4*)(C + (size_t)row * N + n0 + tx * 8) = o0;
        *(float4*)(C + (size_t)row * N + n0 + tx * 8 + 4) = o1;
    }
}

// ---------------- 3) GEMM TN (per batch): C[m,u] = sum_l G[l,m] * t[l,u] ----
// G is (L x L) row-major (K-major over l), t is (L x U). K=1024, lda=1024.
__global__ __launch_bounds__(256) void gemm_tn(const float* __restrict__ A,
                                               const float* __restrict__ Bm,
                                               float* __restrict__ C) {
    __shared__ float As[16][128];
    __shared__ float Bs[16][128];
    const int N = 256, K = L_, lda = L_;
    const int b = blockIdx.z;
    A += (size_t)b * L_ * L_;
    Bm += (size_t)b * L_ * U_;
    C += (size_t)b * L_ * U_;
    const int m0 = blockIdx.y * 128, n0 = blockIdx.x * 128;
    const int t = threadIdx.x;
    const int tx = t & 15, ty = t >> 4;

    ull acc[8][4];
#pragma unroll
    for (int i = 0; i < 8; i++)
#pragma unroll
        for (int j = 0; j < 4; j++) acc[i][j] = 0ull;

    for (int k0 = 0; k0 < K; k0 += 16) {
        __syncthreads();
#pragma unroll
        for (int i = 0; i < 2; i++) {
            int f4 = t + i * 256;
            int kk = f4 >> 5, g = f4 & 31;
            *(float4*)&As[kk][g * 4] =
                *(const float4*)(A + (size_t)(k0 + kk) * lda + m0 + g * 4);
            *(float4*)&Bs[kk][g * 4] =
                *(const float4*)(Bm + (size_t)(k0 + kk) * N + n0 + g * 4);
        }
        __syncthreads();
#pragma unroll
        for (int kk = 0; kk < 16; kk++) {
            float4 a0 = *(float4*)&As[kk][ty * 8];
            float4 a1 = *(float4*)&As[kk][ty * 8 + 4];
            float4 b0 = *(float4*)&Bs[kk][tx * 8];
            float4 b1 = *(float4*)&Bs[kk][tx * 8 + 4];
            ull bp0 = pk2(b0.x, b0.y), bp1 = pk2(b0.z, b0.w);
            ull bp2 = pk2(b1.x, b1.y), bp3 = pk2(b1.z, b1.w);
            float av[8] = {a0.x, a0.y, a0.z, a0.w, a1.x, a1.y, a1.z, a1.w};
#pragma unroll
            for (int i = 0; i < 8; i++) {
                ull ad = pk2(av[i], av[i]);
                ffma2(acc[i][0], ad, bp0);
                ffma2(acc[i][1], ad, bp1);
                ffma2(acc[i][2], ad, bp2);
                ffma2(acc[i][3], ad, bp3);
            }
        }
    }
#pragma unroll
    for (int i = 0; i < 8; i++) {
        int row = m0 + ty * 8 + i;
        float2 v0 = up2(acc[i][0]), v1 = up2(acc[i][1]);
        float2 v2 = up2(acc[i][2]), v3 = up2(acc[i][3]);
        float4 o0 = make_float4(v0.x, v0.y, v1.x, v1.y);
        float4 o1 = make_float4(v2.x, v2.y, v3.x, v3.y);
        *(float4*)(C + (size_t)row * N + n0 + tx * 8) = o0;
        *(float4*)(C + (size_t)row * N + n0 + tx * 8 + 4) = o1;
    }
}

// ---------------- 4) sequential scan: h = tanh(xproj[s] + h @ Wh + b) -------
// One CTA per batch. 256 threads = 1 thread per output u.
// Wh column for u: 192 values (96 f32x2 pairs) in registers, 64 values
// (32 pairs) in SMEM. h double-buffered in SMEM (broadcast reads).
#define SCAN_KRF_PAIRS 96
#define SCAN_SM_PAIRS 32
#define SCAN_SMEM_BYTES (SCAN_SM_PAIRS * 256 * 8 + 2 * 256 * 4)

__global__ __launch_bounds__(256, 1) void scan_kernel(const float* __restrict__ Wh,
                                                      const float* __restrict__ xproj,
                                                      const float* __restrict__ bias,
                                                      float* __restrict__ out) {
    extern __shared__ unsigned char smraw[];
    ull* wsm = (ull*)smraw;                                    // 64 KB: pairs 96..127
    float* hbuf = (float*)(smraw + SCAN_SM_PAIRS * 256 * 8);   // 2 KB: double-buffered h
    const int u = threadIdx.x;
    const int b = blockIdx.x;

    ull wreg[SCAN_KRF_PAIRS];
#pragma unroll
    for (int p = 0; p < SCAN_KRF_PAIRS; p++)
        wreg[p] = pk2(Wh[(2 * p) * U_ + u], Wh[(2 * p + 1) * U_ + u]);
#pragma unroll 8
    for (int j = 0; j < SCAN_SM_PAIRS; j++)
        wsm[j * 256 + u] = pk2(Wh[(2 * SCAN_KRF_PAIRS + 2 * j) * U_ + u],
                               Wh[(2 * SCAN_KRF_PAIRS + 2 * j + 1) * U_ + u]);
    hbuf[u] = 0.f;
    hbuf[256 + u] = 0.f;
    const float bv = bias[u];
    __syncthreads();

    const float* xp = xproj + (size_t)b * L_ * U_ + u;
    float* op = out + (size_t)b * L_ * U_ + u;
    float xv = xp[0];
    int cur = 0;

    for (int s = 0; s < L_; s++) {
        int sn = (s + 1 < L_) ? s + 1 : s;
        float xn = xp[(size_t)sn * U_];  // prefetch next step's x

        const ulonglong2* hp = (const ulonglong2*)(hbuf + cur * 256);
        ull a0 = 0ull, a1 = 0ull, a2 = 0ull, a3 = 0ull;
#pragma unroll
        for (int q = 0; q < SCAN_KRF_PAIRS / 2; q++) {  // pairs 0..95 (RF weights)
            ulonglong2 hv = hp[q];
            if (q & 1) { ffma2(a2, hv.x, wreg[2 * q]); ffma2(a3, hv.y, wreg[2 * q + 1]); }
            else       { ffma2(a0, hv.x, wreg[2 * q]); ffma2(a1, hv.y, wreg[2 * q + 1]); }
        }
#pragma unroll
        for (int j = 0; j < SCAN_SM_PAIRS / 2; j++) {   // pairs 96..127 (SMEM weights)
            ulonglong2 hv = hp[SCAN_KRF_PAIRS / 2 + j];
            ull w0 = wsm[(2 * j) * 256 + u];
            ull w1 = wsm[(2 * j + 1) * 256 + u];
            if (j & 1) { ffma2(a2, hv.x, w0); ffma2(a3, hv.y, w1); }
            else       { ffma2(a0, hv.x, w0); ffma2(a1, hv.y, w1); }
        }
        float2 v0 = up2(a0), v1 = up2(a1), v2 = up2(a2), v3 = up2(a3);
        float z = ((v0.x + v0.y) + (v1.x + v1.y)) +
                  ((v2.x + v2.y) + (v3.x + v3.y)) + xv + bv;
        float h = tanhf(z);
        hbuf[(cur ^ 1) * 256 + u] = h;
        op[(size_t)s * U_] = h;
        xv = xn;
        cur ^= 1;
        __syncthreads();
    }
}

// ---------------- launch --------------------------------------------------
extern "C" void kernel_launch(void* const* d_in, const int* in_sizes, int n_in,
                              void* d_out, int out_size) {
    const float* seq = (const float*)d_in[0];    // (8,1024,256)
    const float* graph = (const float*)d_in[1];  // (8,1024,1024)
    const float* E = (const float*)d_in[2];      // (256,256)
    const float* Wx = (const float*)d_in[3];     // (256,256)
    const float* Wh = (const float*)d_in[4];     // (256,256)
    const float* bias = (const float*)d_in[5];   // (256,)
    float* out = (float*)d_out;                  // (8,1024,256)

    float *ew, *rn, *tt, *xp;
    cudaGetSymbolAddress((void**)&ew, g_EW);
    cudaGetSymbolAddress((void**)&rn, g_rnorm);
    cudaGetSymbolAddress((void**)&tt, g_t);
    cudaGetSymbolAddress((void**)&xp, g_xproj);

    // 1) rnorm
    norm_kernel<<<(B_ * L_) / 8, 256>>>(graph, rn);
    // 2) EW = E @ Wx (256x256x256)
    gemm_nn<<<dim3(2, 2), 256>>>(E, Wx, ew, 256, nullptr);
    // 3) t = (seq @ EW) * rnorm   (M=8192, K=256, N=256)
    gemm_nn<<<dim3(2, 64), 256>>>(seq, ew, tt, 256, rn);
    // 4) xproj[b] = G[b]^T @ t[b] (per batch M=1024, K=1024, N=256)
    gemm_tn<<<dim3(2, 8, 8), 256>>>(graph, tt, xp);
    // 5) scan
    cudaFuncSetAttribute(scan_kernel, cudaFuncAttributeMaxDynamicSharedMemorySize,
                         SCAN_SMEM_BYTES);
    scan_kernel<<<B_, 256, SCAN_SMEM_BYTES>>>(Wh, xp, bias, out);
}

// round 2
// speedup vs baseline: 1.3307x; 1.3307x over previous
#include <cuda_runtime.h>
#include <math.h>

#define B_ 8
#define L_ 1024
#define D_ 256
#define U_ 256

typedef unsigned long long ull;

// ---------------- scratch (device globals; no allocation allowed) ----------
__device__ float g_EW[D_ * U_];          // E @ Wx            (256 KB)
__device__ float g_rnorm[B_ * L_];       // 1/max(rowsum,eps) (32 KB)
__device__ float g_t[B_ * L_ * U_];      // (seq@EW)*rnorm    (8 MB)
__device__ float g_xproj[B_ * L_ * U_];  // G^T @ t           (8 MB)

// ---------------- packed f32x2 helpers (sm_103a) ----------------------------
__device__ __forceinline__ ull pk2(float lo, float hi) {
    ull r; asm("mov.b64 %0,{%1,%2};" : "=l"(r) : "f"(lo), "f"(hi)); return r;
}
__device__ __forceinline__ void ffma2(ull& d, ull a, ull b) {
    asm("fma.rn.f32x2 %0,%1,%2,%0;" : "+l"(d) : "l"(a), "l"(b));
}
__device__ __forceinline__ float2 up2(ull a) {
    float lo, hi; asm("mov.b64 {%0,%1},%2;" : "=f"(lo), "=f"(hi) : "l"(a));
    float2 r; r.x = lo; r.y = hi; return r;
}

// ---------------- 1) rnorm[b,l] = 1 / max(sum_m graph[b,l,m], 1e-7) ---------
__global__ __launch_bounds__(256) void norm_kernel(const float* __restrict__ graph,
                                                   float* __restrict__ rnorm) {
    int warp = (blockIdx.x * blockDim.x + threadIdx.x) >> 5;
    int lane = threadIdx.x & 31;
    if (warp >= B_ * L_) return;
    const float4* row = (const float4*)(graph + (size_t)warp * L_);
    float s = 0.f;
#pragma unroll
    for (int i = lane; i < L_ / 4; i += 32) {
        float4 v = row[i];
        s += (v.x + v.y) + (v.z + v.w);
    }
#pragma unroll
    for (int o = 16; o; o >>= 1) s += __shfl_xor_sync(0xffffffffu, s, o);
    if (lane == 0) rnorm[warp] = 1.f / fmaxf(s, 1e-7f);
}

// ---------------- 2) GEMM NN: C[M,N] = A[M,K] @ B[K,N] (* rowscale) ---------
// 128x128 tile, BK=16, 256 threads, 8x8 micro-tile, f32x2 FMAs.
// Single-sync double-buffered SMEM pipeline with LDG->reg prefetch.
__global__ __launch_bounds__(256) void gemm_nn(const float* __restrict__ A,
                                               const float* __restrict__ Bm,
                                               float* __restrict__ C, int K,
                                               const float* __restrict__ rowscale) {
    __shared__ float As[2][16][128];
    __shared__ float Bs[2][16][128];
    const int N = 256;
    const int m0 = blockIdx.y * 128, n0 = blockIdx.x * 128;
    const int t = threadIdx.x;
    const int tx = t & 15, ty = t >> 4;

    ull acc[8][4];
#pragma unroll
    for (int i = 0; i < 8; i++)
#pragma unroll
        for (int j = 0; j < 4; j++) acc[i][j] = 0ull;

    // per-thread load coordinates
    int am[2], akg[2], bkk[2], bng[2];
#pragma unroll
    for (int i = 0; i < 2; i++) {
        int f4 = t + i * 256;
        am[i] = f4 >> 2; akg[i] = f4 & 3;
        bkk[i] = f4 >> 5; bng[i] = f4 & 31;
    }

    float4 ra[2], rb[2];
#pragma unroll
    for (int i = 0; i < 2; i++) {
        ra[i] = *(const float4*)(A + (size_t)(m0 + am[i]) * K + akg[i] * 4);
        rb[i] = *(const float4*)(Bm + (size_t)bkk[i] * N + n0 + bng[i] * 4);
    }

    int cur = 0;
    for (int k0 = 0; k0 < K; k0 += 16) {
        // store prefetched tile into buffer `cur`
#pragma unroll
        for (int i = 0; i < 2; i++) {
            As[cur][akg[i] * 4 + 0][am[i]] = ra[i].x;
            As[cur][akg[i] * 4 + 1][am[i]] = ra[i].y;
            As[cur][akg[i] * 4 + 2][am[i]] = ra[i].z;
            As[cur][akg[i] * 4 + 3][am[i]] = ra[i].w;
            *(float4*)&Bs[cur][bkk[i]][bng[i] * 4] = rb[i];
        }
        __syncthreads();
        if (k0 + 16 < K) {
#pragma unroll
            for (int i = 0; i < 2; i++) {
                ra[i] = *(const float4*)(A + (size_t)(m0 + am[i]) * K + k0 + 16 + akg[i] * 4);
                rb[i] = *(const float4*)(Bm + (size_t)(k0 + 16 + bkk[i]) * N + n0 + bng[i] * 4);
            }
        }
#pragma unroll
        for (int kk = 0; kk < 16; kk++) {
            float4 a0 = *(float4*)&As[cur][kk][ty * 8];
            float4 a1 = *(float4*)&As[cur][kk][ty * 8 + 4];
            float4 b0 = *(float4*)&Bs[cur][kk][tx * 8];
            float4 b1 = *(float4*)&Bs[cur][kk][tx * 8 + 4];
            ull bp0 = pk2(b0.x, b0.y), bp1 = pk2(b0.z, b0.w);
            ull bp2 = pk2(b1.x, b1.y), bp3 = pk2(b1.z, b1.w);
            float av[8] = {a0.x, a0.y, a0.z, a0.w, a1.x, a1.y, a1.z, a1.w};
#pragma unroll
            for (int i = 0; i < 8; i++) {
                ull ad = pk2(av[i], av[i]);
                ffma2(acc[i][0], ad, bp0);
                ffma2(acc[i][1], ad, bp1);
                ffma2(acc[i][2], ad, bp2);
                ffma2(acc[i][3], ad, bp3);
            }
        }
        cur ^= 1;
    }
#pragma unroll
    for (int i = 0; i < 8; i++) {
        int row = m0 + ty * 8 + i;
        float sc = rowscale ? rowscale[row] : 1.f;
        float2 v0 = up2(acc[i][0]), v1 = up2(acc[i][1]);
        float2 v2 = up2(acc[i][2]), v3 = up2(acc[i][3]);
        float4 o0 = make_float4(v0.x * sc, v0.y * sc, v1.x * sc, v1.y * sc);
        float4 o1 = make_float4(v2.x * sc, v2.y * sc, v3.x * sc, v3.y * sc);
        *(float4*)(C + (size_t)row * N + n0 + tx * 8) = o0;
        *(float4*)(C + (size_t)row * N + n0 + tx * 8 + 4) = o1;
    }
}

// ---------------- 3) GEMM TN (per batch): C[m,u] = sum_l G[l,m] * t[l,u] ----
// Same pipeline as gemm_nn; A read K-major with lda = L.
__global__ __launch_bounds__(256) void gemm_tn(const float* __restrict__ A,
                                               const float* __restrict__ Bm,
                                               float* __restrict__ C) {
    __shared__ float As[2][16][128];
    __shared__ float Bs[2][16][128];
    const int N = 256, K = L_, lda = L_;
    const int b = blockIdx.z;
    A += (size_t)b * L_ * L_;
    Bm += (size_t)b * L_ * U_;
    C += (size_t)b * L_ * U_;
    const int m0 = blockIdx.y * 128, n0 = blockIdx.x * 128;
    const int t = threadIdx.x;
    const int tx = t & 15, ty = t >> 4;

    ull acc[8][4];
#pragma unroll
    for (int i = 0; i < 8; i++)
#pragma unroll
        for (int j = 0; j < 4; j++) acc[i][j] = 0ull;

    int kk_[2], g_[2];
#pragma unroll
    for (int i = 0; i < 2; i++) {
        int f4 = t + i * 256;
        kk_[i] = f4 >> 5; g_[i] = f4 & 31;
    }

    float4 ra[2], rb[2];
#pragma unroll
    for (int i = 0; i < 2; i++) {
        ra[i] = *(const float4*)(A + (size_t)kk_[i] * lda + m0 + g_[i] * 4);
        rb[i] = *(const float4*)(Bm + (size_t)kk_[i] * N + n0 + g_[i] * 4);
    }

    int cur = 0;
    for (int k0 = 0; k0 < K; k0 += 16) {
#pragma unroll
        for (int i = 0; i < 2; i++) {
            *(float4*)&As[cur][kk_[i]][g_[i] * 4] = ra[i];
            *(float4*)&Bs[cur][kk_[i]][g_[i] * 4] = rb[i];
        }
        __syncthreads();
        if (k0 + 16 < K) {
#pragma unroll
            for (int i = 0; i < 2; i++) {
                ra[i] = *(const float4*)(A + (size_t)(k0 + 16 + kk_[i]) * lda + m0 + g_[i] * 4);
                rb[i] = *(const float4*)(Bm + (size_t)(k0 + 16 + kk_[i]) * N + n0 + g_[i] * 4);
            }
        }
#pragma unroll
        for (int kk = 0; kk < 16; kk++) {
            float4 a0 = *(float4*)&As[cur][kk][ty * 8];
            float4 a1 = *(float4*)&As[cur][kk][ty * 8 + 4];
            float4 b0 = *(float4*)&Bs[cur][kk][tx * 8];
            float4 b1 = *(float4*)&Bs[cur][kk][tx * 8 + 4];
            ull bp0 = pk2(b0.x, b0.y), bp1 = pk2(b0.z, b0.w);
            ull bp2 = pk2(b1.x, b1.y), bp3 = pk2(b1.z, b1.w);
            float av[8] = {a0.x, a0.y, a0.z, a0.w, a1.x, a1.y, a1.z, a1.w};
#pragma unroll
            for (int i = 0; i < 8; i++) {
                ull ad = pk2(av[i], av[i]);
                ffma2(acc[i][0], ad, bp0);
                ffma2(acc[i][1], ad, bp1);
                ffma2(acc[i][2], ad, bp2);
                ffma2(acc[i][3], ad, bp3);
            }
        }
        cur ^= 1;
    }
#pragma unroll
    for (int i = 0; i < 8; i++) {
        int row = m0 + ty * 8 + i;
        float2 v0 = up2(acc[i][0]), v1 = up2(acc[i][1]);
        float2 v2 = up2(acc[i][2]), v3 = up2(acc[i][3]);
        float4 o0 = make_float4(v0.x, v0.y, v1.x, v1.y);
        float4 o1 = make_float4(v2.x, v2.y, v3.x, v3.y);
        *(float4*)(C + (size_t)row * N + n0 + tx * 8) = o0;
        *(float4*)(C + (size_t)row * N + n0 + tx * 8 + 4) = o1;
    }
}

// ---------------- 4) sequential scan: h = tanh(xproj[s] + h @ Wh + b) -------
// One CTA per batch, 256 threads = 8 warps.
// Warp w: k-slice ks = w>>1 (64 k values), output half oh = w&1.
// Lane l: 4 outputs u0 = oh*128 + l*4 .. +3.
// Per output: 32 weight pairs over its k-slice; 26 in RF, 6 in SMEM.
// Partial sums part[4][256] reduced by one thread per output.
#define RF_PAIRS 26
#define SM_PAIRS 6
#define WS_ULLS (SM_PAIRS * 4 * 4 * 64)          // 6144 ull = 48 KB
#define SCAN_SMEM_BYTES (WS_ULLS * 8 + 4 * 256 * 4 + 2 * 256 * 4)

__global__ __launch_bounds__(256, 1) void scan_kernel(const float* __restrict__ Wh,
                                                      const float* __restrict__ xproj,
                                                      const float* __restrict__ bias,
                                                      float* __restrict__ out) {
    extern __shared__ unsigned char smraw[];
    ull* ws = (ull*)smraw;                                  // 48 KB weights
    float* part = (float*)(smraw + WS_ULLS * 8);            // 4 KB partials
    float* hbuf = part + 4 * 256;                           // 2 KB h (double buf)

    const int tid = threadIdx.x;
    const int b = blockIdx.x;
    const int w = tid >> 5, l = tid & 31;
    const int ks = w >> 1, oh = w & 1;
    const int u0 = oh * 128 + l * 4;

    // --- fill SMEM weights: ws[((ps*4+ks)*4+j)*64 + oh*32 + l] = pair(k,k+1) for
    //     output u = oh*128 + l*4 + j, k = ks*64 + 2*(26+ps)
    for (int idx = tid; idx < WS_ULLS; idx += 256) {
        int e = idx >> 6, r = idx & 63;
        int ps = e >> 4, ksf = (e >> 2) & 3, jf = e & 3;
        int ohf = r >> 5, lf = r & 31;
        int uf = ohf * 128 + lf * 4 + jf;
        int kf = ksf * 64 + 2 * (RF_PAIRS + ps);
        ws[idx] = pk2(Wh[kf * U_ + uf], Wh[(kf + 1) * U_ + uf]);
    }

    // --- RF weights: wreg[j][p] = pair(k = ks*64+2p) for output u0+j
    ull wreg[4][RF_PAIRS];
#pragma unroll
    for (int j = 0; j < 4; j++)
#pragma unroll
        for (int p = 0; p < RF_PAIRS; p++) {
            int k = ks * 64 + 2 * p;
            wreg[j][p] = pk2(Wh[k * U_ + u0 + j], Wh[(k + 1) * U_ + u0 + j]);
        }

    hbuf[tid] = 0.f;
    hbuf[256 + tid] = 0.f;
    const float bv = bias[tid];
    __syncthreads();

    const float* xp = xproj + (size_t)b * L_ * U_ + tid;
    float* op = out + (size_t)b * L_ * U_ + tid;
    float xv = xp[0];
    int cur = 0;

    // per-thread SMEM weight base (ull index): ps*1024 + j*64 within this
    const ull* wsp = ws + ks * 256 + oh * 32 + l;

    for (int s = 0; s < L_; s++) {
        const ulonglong2* hp2 = (const ulonglong2*)(hbuf + cur * 256 + ks * 64);
        ull a0 = 0ull, a1 = 0ull, a2 = 0ull, a3 = 0ull;
#pragma unroll
        for (int q = 0; q < 13; q++) {   // pairs 0..25 (RF)
            ulonglong2 hv = hp2[q];
            ffma2(a0, hv.x, wreg[0][2 * q]);
            ffma2(a1, hv.x, wreg[1][2 * q]);
            ffma2(a2, hv.x, wreg[2][2 * q]);
            ffma2(a3, hv.x, wreg[3][2 * q]);
            ffma2(a0, hv.y, wreg[0][2 * q + 1]);
            ffma2(a1, hv.y, wreg[1][2 * q + 1]);
            ffma2(a2, hv.y, wreg[2][2 * q + 1]);
            ffma2(a3, hv.y, wreg[3][2 * q + 1]);
        }
#pragma unroll
        for (int qq = 0; qq < 3; qq++) { // pairs 26..31 (SMEM)
            ulonglong2 hv = hp2[13 + qq];
            int ps0 = 2 * qq, ps1 = 2 * qq + 1;
            ffma2(a0, hv.x, wsp[ps0 * 1024 + 0 * 64]);
            ffma2(a1, hv.x, wsp[ps0 * 1024 + 1 * 64]);
            ffma2(a2, hv.x, wsp[ps0 * 1024 + 2 * 64]);
            ffma2(a3, hv.x, wsp[ps0 * 1024 + 3 * 64]);
            ffma2(a0, hv.y, wsp[ps1 * 1024 + 0 * 64]);
            ffma2(a1, hv.y, wsp[ps1 * 1024 + 1 * 64]);
            ffma2(a2, hv.y, wsp[ps1 * 1024 + 2 * 64]);
            ffma2(a3, hv.y, wsp[ps1 * 1024 + 3 * 64]);
        }
        float2 v0 = up2(a0), v1 = up2(a1), v2 = up2(a2), v3 = up2(a3);
        float4 pr = make_float4(v0.x + v0.y, v1.x + v1.y, v2.x + v2.y, v3.x + v3.y);
        *(float4*)&part[ks * 256 + u0] = pr;
        __syncthreads();

        // reduce: thread `tid` owns output u = tid
        float z = part[tid] + part[256 + tid] + part[512 + tid] + part[768 + tid]
                  + xv + bv;
        float h = tanhf(z);
        hbuf[(cur ^ 1) * 256 + tid] = h;
        op[(size_t)s * U_] = h;
        int sn = (s + 1 < L_) ? s + 1 : s;
        xv = xp[(size_t)sn * U_];
        cur ^= 1;
        __syncthreads();
    }
}

// ---------------- launch --------------------------------------------------
extern "C" void kernel_launch(void* const* d_in, const int* in_sizes, int n_in,
                              void* d_out, int out_size) {
    const float* seq = (const float*)d_in[0];    // (8,1024,256)
    const float* graph = (const float*)d_in[1];  // (8,1024,1024)
    const float* E = (const float*)d_in[2];      // (256,256)
    const float* Wx = (const float*)d_in[3];     // (256,256)
    const float* Wh = (const float*)d_in[4];     // (256,256)
    const float* bias = (const float*)d_in[5];   // (256,)
    float* out = (float*)d_out;                  // (8,1024,256)

    float *ew, *rn, *tt, *xp;
    cudaGetSymbolAddress((void**)&ew, g_EW);
    cudaGetSymbolAddress((void**)&rn, g_rnorm);
    cudaGetSymbolAddress((void**)&tt, g_t);
    cudaGetSymbolAddress((void**)&xp, g_xproj);

    // 1) rnorm
    norm_kernel<<<(B_ * L_) / 8, 256>>>(graph, rn);
    // 2) EW = E @ Wx (256x256x256)
    gemm_nn<<<dim3(2, 2), 256>>>(E, Wx, ew, 256, nullptr);
    // 3) t = (seq @ EW) * rnorm   (M=8192, K=256, N=256)
    gemm_nn<<<dim3(2, 64), 256>>>(seq, ew, tt, 256, rn);
    // 4) xproj[b] = G[b]^T @ t[b] (per batch M=1024, K=1024, N=256)
    gemm_tn<<<dim3(2, 8, 8), 256>>>(graph, tt, xp);
    // 5) scan
    cudaFuncSetAttribute(scan_kernel, cudaFuncAttributeMaxDynamicSharedMemorySize,
                         SCAN_SMEM_BYTES);
    scan_kernel<<<B_, 256, SCAN_SMEM_BYTES>>>(Wh, xp, bias, out);
}